// round 12
// baseline (speedup 1.0000x reference)
#include <cuda_runtime.h>
#include <cuda_fp16.h>
#include <math.h>
#include <stdint.h>

#define N_TOK 4096
#define HDIM  1024
#define FDIM  2816
#define NEXP  8
#define NA    (N_TOK * 2)      // assignments (top-2)
#define TM    128              // m-tile rows
#define KB    64               // k halves per chunk = 128 B per smem row
#define STAGE 24576            // A tile 16KB + B tile 8KB
#define NSTG  3
#define SMEM_DYN (NSTG * STAGE)
#define MAXMT 72               // max total m-tiles: 8192/128 + 7

// ---------------- scratch (static device allocations only) ----------------
__device__ float g_scores[NA];
__device__ int   g_eids[NA];
__device__ int   g_cnt[NEXP];
__device__ int   g_fill[NEXP];
__device__ int   g_off[NEXP + 1];
__device__ int   g_tileoff[NEXP + 1];
__device__ int   g_rows[NA];     // sorted pos -> token
__device__ int   g_aid[NA];      // sorted pos -> assignment id
__device__ __align__(16) __half g_xh[(size_t)N_TOK * HDIM];
__device__ __align__(16) __half g_w1h[(size_t)NEXP * 2 * FDIM * HDIM];
__device__ __align__(16) __half g_w2h[(size_t)NEXP * HDIM * FDIM];
__device__ __align__(16) __half g_Gh[(size_t)NA * FDIM];   // GLU output fp16

// ---------------- helpers ----------------
__device__ __forceinline__ uint32_t smem_u32(const void* p) {
    uint32_t a;
    asm("{ .reg .u64 t; cvta.to.shared.u64 t, %1; cvt.u32.u64 %0, t; }" : "=r"(a) : "l"(p));
    return a;
}
__device__ __forceinline__ uint32_t sw(uint32_t off) {   // SW128 swizzle: chunk ^= row&7
    return off ^ ((off >> 3) & 0x70);
}
#define CP16(dst, src) \
    asm volatile("cp.async.cg.shared.global [%0], [%1], 16;" :: "r"(dst), "l"(src))
#define CPCOMMIT() asm volatile("cp.async.commit_group;" ::: "memory")
#define CPWAIT1()  asm volatile("cp.async.wait_group 1;" ::: "memory")
#define CPWAIT0()  asm volatile("cp.async.wait_group 0;" ::: "memory")
#define LDM4(r0, r1, r2, r3, addr) \
    asm volatile("ldmatrix.sync.aligned.m8n8.x4.shared.b16 {%0,%1,%2,%3},[%4];" \
                 : "=r"(r0), "=r"(r1), "=r"(r2), "=r"(r3) : "r"(addr))
__device__ __forceinline__ void mma16(float* d, const uint32_t* a, uint32_t b0, uint32_t b1) {
    asm volatile(
        "mma.sync.aligned.m16n8k16.row.col.f32.f16.f16.f32 "
        "{%0,%1,%2,%3},{%4,%5,%6,%7},{%8,%9},{%0,%1,%2,%3};"
        : "+f"(d[0]), "+f"(d[1]), "+f"(d[2]), "+f"(d[3])
        : "r"(a[0]), "r"(a[1]), "r"(a[2]), "r"(a[3]), "r"(b0), "r"(b1));
}
// fragment loads (A: 2 x ldmatrix.x4 by mi; B: 1 x ldmatrix.x4 per (j,p))
#define LDAF(dst, sbase, j) do { \
    LDM4((dst)[0][0], (dst)[0][1], (dst)[0][2], (dst)[0][3], (sbase) + sw(aoff[0] + (j) * 32)); \
    LDM4((dst)[1][0], (dst)[1][1], (dst)[1][2], (dst)[1][3], (sbase) + sw(aoff[1] + (j) * 32)); \
} while (0)
#define LDBF(dst, sbase, j, p) \
    LDM4((dst)[0], (dst)[1], (dst)[2], (dst)[3], (sbase) + sw(boff[p] + (j) * 32))

// ---------------- launch 0: weight convert + counter init + out zero ----------
__global__ void convert_kernel(const float* __restrict__ w1, const float* __restrict__ w2,
                               float* __restrict__ out) {
    if (blockIdx.x == 0 && threadIdx.x < NEXP) {
        g_cnt[threadIdx.x] = 0; g_fill[threadIdx.x] = 0;
    }
    if (blockIdx.x < N_TOK) {
        ((float4*)out)[(size_t)blockIdx.x * 256 + threadIdx.x] =
            make_float4(0.f, 0.f, 0.f, 0.f);
    }
    const size_t U1 = (size_t)NEXP * 2 * FDIM * HDIM / 8;
    const size_t U2 = (size_t)NEXP * HDIM * FDIM / 8;
    const size_t i = (size_t)blockIdx.x * blockDim.x + threadIdx.x;
    const float* src;
    __half* dst;
    if (i < U1)           { src = w1 + i * 8;        dst = g_w1h + i * 8; }
    else if (i < U1 + U2) { src = w2 + (i - U1) * 8; dst = g_w2h + (i - U1) * 8; }
    else return;
    const float4 v0 = ((const float4*)src)[0];
    const float4 v1 = ((const float4*)src)[1];
    __half2 h0 = __floats2half2_rn(v0.x, v0.y);
    __half2 h1 = __floats2half2_rn(v0.z, v0.w);
    __half2 h2 = __floats2half2_rn(v1.x, v1.y);
    __half2 h3 = __floats2half2_rn(v1.z, v1.w);
    uint4 o;
    o.x = *(uint32_t*)&h0; o.y = *(uint32_t*)&h1;
    o.z = *(uint32_t*)&h2; o.w = *(uint32_t*)&h3;
    *(uint4*)dst = o;
}

// ---------------- launch 1: router (+ x fp16 convert) ----------------
__global__ __launch_bounds__(256) void router_kernel(const float* __restrict__ x,
                                                     const float* __restrict__ wqkv) {
    __shared__ float sx[HDIM];
    __shared__ float sqkv[3 * NEXP];
    const int t = blockIdx.x;
    const float* xr = x + (size_t)t * HDIM;
    for (int i = threadIdx.x; i < HDIM; i += blockDim.x) sx[i] = xr[i];
    __syncthreads();

    for (int i = threadIdx.x; i < HDIM; i += blockDim.x)
        g_xh[(size_t)t * HDIM + i] = __float2half(sx[i]);

    const int w = threadIdx.x >> 5, lane = threadIdx.x & 31;
    #pragma unroll
    for (int r = 0; r < 3; r++) {
        const int j = w + r * NEXP;
        const float* wr = wqkv + (size_t)j * HDIM;
        float s = 0.f;
        for (int i = lane; i < HDIM; i += 32) s += sx[i] * wr[i];
        #pragma unroll
        for (int o = 16; o; o >>= 1) s += __shfl_xor_sync(0xffffffffu, s, o);
        if (lane == 0) sqkv[j] = s;
    }
    __syncthreads();

    if (w == 0) {
        float logit = -1e30f;
        if (lane < NEXP) {
            const float qe = sqkv[lane];
            float a[NEXP], m = -1e30f;
            #pragma unroll
            for (int j = 0; j < NEXP; j++) { a[j] = qe * sqkv[8 + j]; m = fmaxf(m, a[j]); }
            float den = 0.f, num = 0.f;
            #pragma unroll
            for (int j = 0; j < NEXP; j++) {
                float ee = expf(a[j] - m);
                den += ee; num += ee * sqkv[16 + j];
            }
            logit = num / den;
        }
        float lg[NEXP];
        #pragma unroll
        for (int e = 0; e < NEXP; e++) lg[e] = __shfl_sync(0xffffffffu, logit, e);
        if (lane == 0) {
            int i0 = 0;
            #pragma unroll
            for (int e = 1; e < NEXP; e++) if (lg[e] > lg[i0]) i0 = e;
            int i1 = (i0 == 0) ? 1 : 0;
            #pragma unroll
            for (int e = 0; e < NEXP; e++) if (e != i1 && e != i0 && lg[e] > lg[i1]) i1 = e;
            const float e1 = expf(lg[i1] - lg[i0]);
            const float inv = 1.f / (1.f + e1);
            g_scores[2 * t]     = inv;
            g_scores[2 * t + 1] = e1 * inv;
            g_eids[2 * t]     = i0;
            g_eids[2 * t + 1] = i1;
            atomicAdd(&g_cnt[i0], 1);
            atomicAdd(&g_cnt[i1], 1);
        }
    }
}

// ---------------- launch 2: scatter (each block re-derives the 8-expert scan) --
__global__ void scatter_kernel() {
    int off[NEXP + 1], tileoff[NEXP + 1];
    int o = 0, tt = 0;
    #pragma unroll
    for (int e = 0; e < NEXP; e++) {
        off[e] = o; tileoff[e] = tt;
        o += g_cnt[e];
        tt += (g_cnt[e] + TM - 1) / TM;
    }
    off[NEXP] = o; tileoff[NEXP] = tt;

    if (blockIdx.x == 0 && threadIdx.x == 0) {
        #pragma unroll
        for (int e = 0; e <= NEXP; e++) { g_off[e] = off[e]; g_tileoff[e] = tileoff[e]; }
    }

    const int a = blockIdx.x * blockDim.x + threadIdx.x;
    if (a < NA) {
        const int e = g_eids[a];
        const int p = off[e] + atomicAdd(&g_fill[e], 1);
        g_aid[p]  = a;
        g_rows[p] = a >> 1;
    }
}

// ---------------- launch 3: grouped GEMM1 (fp16 HMMA) + fused GLU -------------
// 256 threads, 3 CTAs/SM. CTA tile: m128 x 32 GLU cols (64 a/g-interleaved B rows).
// Per-warp m32n32 (acc 32 regs); warps 4m x 2n; B ring-3, A ping-pong.
__global__ __launch_bounds__(256, 3) void gemm1_kernel() {
    const int mt = blockIdx.x;
    if (mt >= g_tileoff[NEXP]) return;
    int e = 0;
    #pragma unroll
    for (int i = 1; i < NEXP; i++) if (g_tileoff[i] <= mt) e = i;
    const int pbase = g_off[e];
    const int cnt   = g_off[e + 1] - pbase;
    const int m0    = (mt - g_tileoff[e]) * TM;
    const int nb    = blockIdx.y * 32;            // GLU col base (64 B rows)

    extern __shared__ __align__(1024) char smem[];
    const uint32_t sb = smem_u32(smem);
    const int tid = threadIdx.x, wid = tid >> 5, lane = tid & 31;
    const int wm = wid & 3, wn = wid >> 2;
    const int sel = lane >> 3, li = lane & 7;
    const int g = lane >> 2, tg = lane & 3;

    // staging maps: A row tid>>1 (128 rows), half tid&1; B row tid>>2 (64 rows), quarter tid&3
    const int r = tid >> 1, hh = tid & 1;
    int am = m0 + r; if (am >= cnt) am = cnt - 1;
    const char* asrc = (const char*)(g_xh + (size_t)g_rows[pbase + am] * HDIM) + hh * 64;
    const int rb = tid >> 2, qq = tid & 3;
    const int wrow = e * 2 * FDIM + ((rb & 1) ? FDIM : 0) + nb + (rb >> 1);  // a/g interleave
    const char* bsrc = (const char*)(g_w1h + (size_t)wrow * HDIM) + qq * 32;
    uint32_t adst[4], bdst[2];
    #pragma unroll
    for (int i = 0; i < 4; i++)
        adst[i] = sw((uint32_t)(r * 128 + hh * 64 + i * 16));
    #pragma unroll
    for (int i = 0; i < 2; i++)
        bdst[i] = 16384 + sw((uint32_t)(rb * 128 + qq * 32 + i * 16));

    uint32_t aoff[2], boff[2];
    #pragma unroll
    for (int mi = 0; mi < 2; mi++)
        aoff[mi] = (uint32_t)(wm * 32 + mi * 16 + (sel & 1) * 8 + li) * 128 + (sel >> 1) * 16;
    #pragma unroll
    for (int p = 0; p < 2; p++)
        boff[p] = 16384 + (uint32_t)(wn * 32 + p * 16 + (sel >> 1) * 8 + li) * 128 + (sel & 1) * 16;

    float acc[2][4][4];
    #pragma unroll
    for (int mi = 0; mi < 2; mi++)
        #pragma unroll
        for (int ni = 0; ni < 4; ni++)
            #pragma unroll
            for (int q = 0; q < 4; q++) acc[mi][ni][q] = 0.f;

    auto stage = [&](int c, int s) {
        const uint32_t base = sb + s * STAGE;
        const char* ga = asrc + (size_t)c * 128;
        const char* gb = bsrc + (size_t)c * 128;
        #pragma unroll
        for (int i = 0; i < 4; i++) CP16(base + adst[i], ga + i * 16);
        #pragma unroll
        for (int i = 0; i < 2; i++) CP16(base + bdst[i], gb + i * 16);
        CPCOMMIT();
    };

    uint32_t af[2][2][4], bf[3][4];
    const int NC = HDIM / KB;  // 16
    stage(0, 0); stage(1, 1);
    CPWAIT1();
    __syncthreads();

    for (int c = 0; c < NC; c++) {
        const uint32_t sbase = sb + (c % NSTG) * STAGE;
        LDAF(af[0], sbase, 0);
        LDBF(bf[0], sbase, 0, 0);
        LDBF(bf[1], sbase, 0, 1);
        #pragma unroll
        for (int t = 0; t < 8; t++) {
            const int j = t >> 1, p = t & 1;
            if (t + 2 < 8) LDBF(bf[(t + 2) % 3], sbase, (t + 2) >> 1, (t + 2) & 1);
            if (p == 0 && j < 3) LDAF(af[(j + 1) & 1], sbase, j + 1);
            #pragma unroll
            for (int mi = 0; mi < 2; mi++) {
                mma16(acc[mi][2 * p],     af[j & 1][mi], bf[t % 3][0], bf[t % 3][1]);
                mma16(acc[mi][2 * p + 1], af[j & 1][mi], bf[t % 3][2], bf[t % 3][3]);
            }
        }
        if (c + 1 < NC) {
            if (c + 2 < NC) { stage(c + 2, (c + 2) % NSTG); CPWAIT1(); }
            else            { CPWAIT0(); }
            __syncthreads();
        }
    }

    // GLU epilogue: even/odd acc cols = (a, g) of GLU col nb + wn*16 + ni*4 + tg
    #pragma unroll
    for (int mi = 0; mi < 2; mi++)
        #pragma unroll
        for (int h = 0; h < 2; h++) {
            const int m = m0 + wm * 32 + mi * 16 + g + h * 8;
            if (m < cnt) {
                __half* gp = g_Gh + (size_t)(pbase + m) * FDIM + nb + wn * 16;
                #pragma unroll
                for (int ni = 0; ni < 4; ni++) {
                    const float a  = acc[mi][ni][h * 2];
                    const float gg = acc[mi][ni][h * 2 + 1];
                    gp[ni * 4 + tg] = __float2half(a / (1.f + expf(-a)) * gg);
                }
            }
        }
}

// ---------------- launch 4: grouped GEMM2 (fp16 HMMA) + score + atomic combine
// CTA tile m128 x n64; per-warp m32n32; 3 CTAs/SM.
__global__ __launch_bounds__(256, 3) void gemm2_kernel(float* __restrict__ out) {
    const int mt = blockIdx.x;
    if (mt >= g_tileoff[NEXP]) return;
    int e = 0;
    #pragma unroll
    for (int i = 1; i < NEXP; i++) if (g_tileoff[i] <= mt) e = i;
    const int pbase = g_off[e];
    const int cnt   = g_off[e + 1] - pbase;
    const int m0    = (mt - g_tileoff[e]) * TM;
    const int nb    = blockIdx.y * 64;            // output col base (64 B rows)

    extern __shared__ __align__(1024) char smem[];
    const uint32_t sb = smem_u32(smem);
    const int tid = threadIdx.x, wid = tid >> 5, lane = tid & 31;
    const int wm = wid & 3, wn = wid >> 2;
    const int sel = lane >> 3, li = lane & 7;
    const int g = lane >> 2, tg = lane & 3;

    const int r = tid >> 1, hh = tid & 1;
    int am = m0 + r; if (am >= cnt) am = cnt - 1;
    const char* asrc = (const char*)(g_Gh + (size_t)(pbase + am) * FDIM) + hh * 64;
    const int rb = tid >> 2, qq = tid & 3;
    const char* bsrc = (const char*)(g_w2h + ((size_t)e * HDIM + nb + rb) * FDIM) + qq * 32;
    uint32_t adst[4], bdst[2];
    #pragma unroll
    for (int i = 0; i < 4; i++)
        adst[i] = sw((uint32_t)(r * 128 + hh * 64 + i * 16));
    #pragma unroll
    for (int i = 0; i < 2; i++)
        bdst[i] = 16384 + sw((uint32_t)(rb * 128 + qq * 32 + i * 16));

    uint32_t aoff[2], boff[2];
    #pragma unroll
    for (int mi = 0; mi < 2; mi++)
        aoff[mi] = (uint32_t)(wm * 32 + mi * 16 + (sel & 1) * 8 + li) * 128 + (sel >> 1) * 16;
    #pragma unroll
    for (int p = 0; p < 2; p++)
        boff[p] = 16384 + (uint32_t)(wn * 32 + p * 16 + (sel >> 1) * 8 + li) * 128 + (sel & 1) * 16;

    float acc[2][4][4];
    #pragma unroll
    for (int mi = 0; mi < 2; mi++)
        #pragma unroll
        for (int ni = 0; ni < 4; ni++)
            #pragma unroll
            for (int q = 0; q < 4; q++) acc[mi][ni][q] = 0.f;

    auto stage = [&](int c, int s) {
        const uint32_t base = sb + s * STAGE;
        const char* ga = asrc + (size_t)c * 128;
        const char* gb = bsrc + (size_t)c * 128;
        #pragma unroll
        for (int i = 0; i < 4; i++) CP16(base + adst[i], ga + i * 16);
        #pragma unroll
        for (int i = 0; i < 2; i++) CP16(base + bdst[i], gb + i * 16);
        CPCOMMIT();
    };

    uint32_t af[2][2][4], bf[3][4];
    const int NC = FDIM / KB;  // 44
    stage(0, 0); stage(1, 1);
    CPWAIT1();
    __syncthreads();

    for (int c = 0; c < NC; c++) {
        const uint32_t sbase = sb + (c % NSTG) * STAGE;
        LDAF(af[0], sbase, 0);
        LDBF(bf[0], sbase, 0, 0);
        LDBF(bf[1], sbase, 0, 1);
        #pragma unroll
        for (int t = 0; t < 8; t++) {
            const int j = t >> 1, p = t & 1;
            if (t + 2 < 8) LDBF(bf[(t + 2) % 3], sbase, (t + 2) >> 1, (t + 2) & 1);
            if (p == 0 && j < 3) LDAF(af[(j + 1) & 1], sbase, j + 1);
            #pragma unroll
            for (int mi = 0; mi < 2; mi++) {
                mma16(acc[mi][2 * p],     af[j & 1][mi], bf[t % 3][0], bf[t % 3][1]);
                mma16(acc[mi][2 * p + 1], af[j & 1][mi], bf[t % 3][2], bf[t % 3][3]);
            }
        }
        if (c + 1 < NC) {
            if (c + 2 < NC) { stage(c + 2, (c + 2) % NSTG); CPWAIT1(); }
            else            { CPWAIT0(); }
            __syncthreads();
        }
    }

    // epilogue: scale by routing score, atomic top-2 combine (2 adds/cell -> deterministic)
    #pragma unroll
    for (int mi = 0; mi < 2; mi++)
        #pragma unroll
        for (int h = 0; h < 2; h++) {
            const int m = m0 + wm * 32 + mi * 16 + g + h * 8;
            if (m < cnt) {
                const int aid  = g_aid[pbase + m];
                const float sc = g_scores[aid];
                float* op = out + (size_t)(aid >> 1) * HDIM + nb + wn * 32;
                #pragma unroll
                for (int ni = 0; ni < 4; ni++) {
                    const int c0 = ni * 8 + 2 * tg;
                    atomicAdd(op + c0,     sc * acc[mi][ni][h * 2]);
                    atomicAdd(op + c0 + 1, sc * acc[mi][ni][h * 2 + 1]);
                }
            }
        }
}

// ---------------- launch ----------------
extern "C" void kernel_launch(void* const* d_in, const int* in_sizes, int n_in,
                              void* d_out, int out_size) {
    const float* x    = (const float*)d_in[0];  // (2,2048,1024)
    const float* wqkv = (const float*)d_in[1];  // (24,1024)
    const float* w1   = (const float*)d_in[2];  // (8,5632,1024)
    const float* w2   = (const float*)d_in[3];  // (8,1024,2816)
    float* out = (float*)d_out;

    cudaFuncSetAttribute(gemm1_kernel, cudaFuncAttributeMaxDynamicSharedMemorySize, SMEM_DYN);
    cudaFuncSetAttribute(gemm2_kernel, cudaFuncAttributeMaxDynamicSharedMemorySize, SMEM_DYN);

    const int conv_units = (NEXP * 2 * FDIM * HDIM + NEXP * HDIM * FDIM) / 8;
    convert_kernel<<<(conv_units + 255) / 256, 256>>>(w1, w2, out);       // 0
    router_kernel<<<N_TOK, 256>>>(x, wqkv);                               // 1
    scatter_kernel<<<(NA + 255) / 256, 256>>>();                          // 2
    gemm1_kernel<<<dim3(MAXMT, FDIM / 32), 256, SMEM_DYN>>>();            // 3  <- profiled
    gemm2_kernel<<<dim3(MAXMT, HDIM / 64), 256, SMEM_DYN>>>(out);         // 4
}

// round 13
// speedup vs baseline: 1.0180x; 1.0180x over previous
#include <cuda_runtime.h>
#include <cuda_fp16.h>
#include <math.h>
#include <stdint.h>

#define N_TOK 4096
#define HDIM  1024
#define FDIM  2816
#define NEXP  8
#define NA    (N_TOK * 2)      // assignments (top-2)
#define TM    128              // m-tile rows
#define KB    64               // k halves per chunk = 128 B per smem row
#define STAGE 32768            // A tile 16KB + B tile 16KB
#define NSTG  3
#define SMEM_DYN (NSTG * STAGE)
#define MAXMT 72               // max total m-tiles: 8192/128 + 7
#define NY1   (FDIM / 64)      // 44 gemm1 y-slices (= gemm2 k-chunks)
#define G1TILES (MAXMT * NY1)  // 3168
#define G2TILES (MAXMT * (HDIM / 128))  // 576

// ---------------- scratch (static device allocations only) ----------------
__device__ float g_scores[NA];
__device__ int   g_eids[NA];
__device__ int   g_cnt[NEXP];
__device__ int   g_fill[NEXP];
__device__ int   g_off[NEXP + 1];
__device__ int   g_tileoff[NEXP + 1];
__device__ int   g_rows[NA];     // sorted pos -> token
__device__ int   g_aid[NA];      // sorted pos -> assignment id
__device__ int   g_flag[G1TILES];  // per-(mtile, y-slice) G-ready flags
__device__ __align__(16) __half g_xh[(size_t)N_TOK * HDIM];
__device__ __align__(16) __half g_w1h[(size_t)NEXP * 2 * FDIM * HDIM];
__device__ __align__(16) __half g_w2h[(size_t)NEXP * HDIM * FDIM];
__device__ __align__(16) __half g_Gh[(size_t)NA * FDIM];   // GLU output fp16

// ---------------- helpers ----------------
__device__ __forceinline__ uint32_t smem_u32(const void* p) {
    uint32_t a;
    asm("{ .reg .u64 t; cvta.to.shared.u64 t, %1; cvt.u32.u64 %0, t; }" : "=r"(a) : "l"(p));
    return a;
}
__device__ __forceinline__ uint32_t sw(uint32_t off) {   // SW128 swizzle: chunk ^= row&7
    return off ^ ((off >> 3) & 0x70);
}
#define CP16(dst, src) \
    asm volatile("cp.async.cg.shared.global [%0], [%1], 16;" :: "r"(dst), "l"(src))
#define CPCOMMIT() asm volatile("cp.async.commit_group;" ::: "memory")
#define CPWAIT1()  asm volatile("cp.async.wait_group 1;" ::: "memory")
#define CPWAIT0()  asm volatile("cp.async.wait_group 0;" ::: "memory")
#define LDM4(r0, r1, r2, r3, addr) \
    asm volatile("ldmatrix.sync.aligned.m8n8.x4.shared.b16 {%0,%1,%2,%3},[%4];" \
                 : "=r"(r0), "=r"(r1), "=r"(r2), "=r"(r3) : "r"(addr))
__device__ __forceinline__ void mma16(float* d, const uint32_t* a, uint32_t b0, uint32_t b1) {
    asm volatile(
        "mma.sync.aligned.m16n8k16.row.col.f32.f16.f16.f32 "
        "{%0,%1,%2,%3},{%4,%5,%6,%7},{%8,%9},{%0,%1,%2,%3};"
        : "+f"(d[0]), "+f"(d[1]), "+f"(d[2]), "+f"(d[3])
        : "r"(a[0]), "r"(a[1]), "r"(a[2]), "r"(a[3]), "r"(b0), "r"(b1));
}
#define LDAF(dst, sbase, j) do { \
    LDM4((dst)[0][0], (dst)[0][1], (dst)[0][2], (dst)[0][3], (sbase) + sw(aoff[0] + (j) * 32)); \
    LDM4((dst)[1][0], (dst)[1][1], (dst)[1][2], (dst)[1][3], (sbase) + sw(aoff[1] + (j) * 32)); \
} while (0)
#define LDBF(dst, sbase, j, p) \
    LDM4((dst)[0], (dst)[1], (dst)[2], (dst)[3], (sbase) + sw(boff[p] + (j) * 32))

__device__ __forceinline__ void spin_flag(int idx) {
    while (atomicAdd(&g_flag[idx], 0) == 0) __nanosleep(200);
}

// ---------------- launch 0: weight convert + counter/flag init + out zero -----
__global__ void convert_kernel(const float* __restrict__ w1, const float* __restrict__ w2,
                               float* __restrict__ out) {
    if (blockIdx.x == 0 && threadIdx.x < NEXP) {
        g_cnt[threadIdx.x] = 0; g_fill[threadIdx.x] = 0;
    }
    if (blockIdx.x == 1) {
        for (int i = threadIdx.x; i < G1TILES; i += 256) g_flag[i] = 0;
    }
    if (blockIdx.x < N_TOK) {
        ((float4*)out)[(size_t)blockIdx.x * 256 + threadIdx.x] =
            make_float4(0.f, 0.f, 0.f, 0.f);
    }
    const size_t U1 = (size_t)NEXP * 2 * FDIM * HDIM / 8;
    const size_t U2 = (size_t)NEXP * HDIM * FDIM / 8;
    const size_t i = (size_t)blockIdx.x * blockDim.x + threadIdx.x;
    const float* src;
    __half* dst;
    if (i < U1)           { src = w1 + i * 8;        dst = g_w1h + i * 8; }
    else if (i < U1 + U2) { src = w2 + (i - U1) * 8; dst = g_w2h + (i - U1) * 8; }
    else return;
    const float4 v0 = ((const float4*)src)[0];
    const float4 v1 = ((const float4*)src)[1];
    __half2 h0 = __floats2half2_rn(v0.x, v0.y);
    __half2 h1 = __floats2half2_rn(v0.z, v0.w);
    __half2 h2 = __floats2half2_rn(v1.x, v1.y);
    __half2 h3 = __floats2half2_rn(v1.z, v1.w);
    uint4 o;
    o.x = *(uint32_t*)&h0; o.y = *(uint32_t*)&h1;
    o.z = *(uint32_t*)&h2; o.w = *(uint32_t*)&h3;
    *(uint4*)dst = o;
}

// ---------------- launch 1: router (+ x fp16 convert) ----------------
__global__ __launch_bounds__(256) void router_kernel(const float* __restrict__ x,
                                                     const float* __restrict__ wqkv) {
    __shared__ float sx[HDIM];
    __shared__ float sqkv[3 * NEXP];
    const int t = blockIdx.x;
    const float* xr = x + (size_t)t * HDIM;
    for (int i = threadIdx.x; i < HDIM; i += blockDim.x) sx[i] = xr[i];
    __syncthreads();

    for (int i = threadIdx.x; i < HDIM; i += blockDim.x)
        g_xh[(size_t)t * HDIM + i] = __float2half(sx[i]);

    const int w = threadIdx.x >> 5, lane = threadIdx.x & 31;
    #pragma unroll
    for (int r = 0; r < 3; r++) {
        const int j = w + r * NEXP;
        const float* wr = wqkv + (size_t)j * HDIM;
        float s = 0.f;
        for (int i = lane; i < HDIM; i += 32) s += sx[i] * wr[i];
        #pragma unroll
        for (int o = 16; o; o >>= 1) s += __shfl_xor_sync(0xffffffffu, s, o);
        if (lane == 0) sqkv[j] = s;
    }
    __syncthreads();

    if (w == 0) {
        float logit = -1e30f;
        if (lane < NEXP) {
            const float qe = sqkv[lane];
            float a[NEXP], m = -1e30f;
            #pragma unroll
            for (int j = 0; j < NEXP; j++) { a[j] = qe * sqkv[8 + j]; m = fmaxf(m, a[j]); }
            float den = 0.f, num = 0.f;
            #pragma unroll
            for (int j = 0; j < NEXP; j++) {
                float ee = expf(a[j] - m);
                den += ee; num += ee * sqkv[16 + j];
            }
            logit = num / den;
        }
        float lg[NEXP];
        #pragma unroll
        for (int e = 0; e < NEXP; e++) lg[e] = __shfl_sync(0xffffffffu, logit, e);
        if (lane == 0) {
            int i0 = 0;
            #pragma unroll
            for (int e = 1; e < NEXP; e++) if (lg[e] > lg[i0]) i0 = e;
            int i1 = (i0 == 0) ? 1 : 0;
            #pragma unroll
            for (int e = 0; e < NEXP; e++) if (e != i1 && e != i0 && lg[e] > lg[i1]) i1 = e;
            const float e1 = expf(lg[i1] - lg[i0]);
            const float inv = 1.f / (1.f + e1);
            g_scores[2 * t]     = inv;
            g_scores[2 * t + 1] = e1 * inv;
            g_eids[2 * t]     = i0;
            g_eids[2 * t + 1] = i1;
            atomicAdd(&g_cnt[i0], 1);
            atomicAdd(&g_cnt[i1], 1);
        }
    }
}

// ---------------- launch 2: scatter (each block re-derives the 8-expert scan) --
__global__ void scatter_kernel() {
    int off[NEXP + 1], tileoff[NEXP + 1];
    int o = 0, tt = 0;
    #pragma unroll
    for (int e = 0; e < NEXP; e++) {
        off[e] = o; tileoff[e] = tt;
        o += g_cnt[e];
        tt += (g_cnt[e] + TM - 1) / TM;
    }
    off[NEXP] = o; tileoff[NEXP] = tt;

    if (blockIdx.x == 0 && threadIdx.x == 0) {
        #pragma unroll
        for (int e = 0; e <= NEXP; e++) { g_off[e] = off[e]; g_tileoff[e] = tileoff[e]; }
    }

    const int a = blockIdx.x * blockDim.x + threadIdx.x;
    if (a < NA) {
        const int e = g_eids[a];
        const int p = off[e] + atomicAdd(&g_fill[e], 1);
        g_aid[p]  = a;
        g_rows[p] = a >> 1;
    }
}

// ---------------- launch 3: FUSED grouped GEMM1 (+GLU) -> GEMM2 (+combine) ----
// bx < G1TILES: gemm1 tile (mt = bx % MAXMT, nbi = bx / MAXMT). After writing
// its 64 G cols it sets g_flag[mt*NY1+nbi]. bx >= G1TILES: gemm2 tile; its
// k-chunk c consumes exactly gemm1 slice nbi == c, so it spins on that flag
// before staging chunk c. Producers dispatch before consumers (bid order).
__global__ __launch_bounds__(256, 2) void gemm_fused_kernel(float* __restrict__ out) {
    extern __shared__ __align__(1024) char smem[];
    const uint32_t sb = smem_u32(smem);
    const int tid = threadIdx.x, wid = tid >> 5, lane = tid & 31;
    const int wm = wid & 3, wn = wid >> 2;
    const int sel = lane >> 3, li = lane & 7;
    const int g = lane >> 2, tg = lane & 3;

    uint32_t aoff[2], boff[4];
    #pragma unroll
    for (int mi = 0; mi < 2; mi++)
        aoff[mi] = (uint32_t)(wm * 32 + mi * 16 + (sel & 1) * 8 + li) * 128 + (sel >> 1) * 16;
    #pragma unroll
    for (int p = 0; p < 4; p++)
        boff[p] = 16384 + (uint32_t)(wn * 64 + p * 16 + (sel >> 1) * 8 + li) * 128 + (sel & 1) * 16;

    float acc[2][8][4];
    #pragma unroll
    for (int mi = 0; mi < 2; mi++)
        #pragma unroll
        for (int ni = 0; ni < 8; ni++)
            #pragma unroll
            for (int q = 0; q < 4; q++) acc[mi][ni][q] = 0.f;

    uint32_t af[2][2][4], bf[3][4];

    if (blockIdx.x < G1TILES) {
        // ================= GEMM1: m128 x 64 GLU cols, K=1024 =================
        const int mt  = blockIdx.x % MAXMT;
        const int nbi = blockIdx.x / MAXMT;
        if (mt >= g_tileoff[NEXP]) return;
        int e = 0;
        #pragma unroll
        for (int i = 1; i < NEXP; i++) if (g_tileoff[i] <= mt) e = i;
        const int pbase = g_off[e];
        const int cnt   = g_off[e + 1] - pbase;
        const int m0    = (mt - g_tileoff[e]) * TM;
        const int nb    = nbi * 64;

        const int r = tid >> 1, hh = tid & 1;
        int am = m0 + r; if (am >= cnt) am = cnt - 1;
        const char* asrc = (const char*)(g_xh + (size_t)g_rows[pbase + am] * HDIM) + hh * 64;
        const int wrow = e * 2 * FDIM + ((r & 1) ? FDIM : 0) + nb + (r >> 1);  // a/g interleave
        const char* bsrc = (const char*)(g_w1h + (size_t)wrow * HDIM) + hh * 64;
        uint32_t adst[4];
        #pragma unroll
        for (int i = 0; i < 4; i++)
            adst[i] = sw((uint32_t)(r * 128 + hh * 64 + i * 16));

        auto stage = [&](int c, int s) {
            const uint32_t base = sb + s * STAGE;
            const char* ga = asrc + (size_t)c * 128;
            const char* gb = bsrc + (size_t)c * 128;
            #pragma unroll
            for (int i = 0; i < 4; i++) CP16(base + adst[i], ga + i * 16);
            #pragma unroll
            for (int i = 0; i < 4; i++) CP16(base + adst[i] + 16384, gb + i * 16);
            CPCOMMIT();
        };

        const int NC = HDIM / KB;  // 16
        stage(0, 0); stage(1, 1);
        CPWAIT1();
        __syncthreads();

        for (int c = 0; c < NC; c++) {
            const uint32_t sbase = sb + (c % NSTG) * STAGE;
            LDAF(af[0], sbase, 0);
            LDBF(bf[0], sbase, 0, 0);
            LDBF(bf[1], sbase, 0, 1);
            #pragma unroll
            for (int t = 0; t < 16; t++) {
                const int j = t >> 2, p = t & 3;
                if (t + 2 < 16) LDBF(bf[(t + 2) % 3], sbase, (t + 2) >> 2, (t + 2) & 3);
                if (p == 1 && j < 3) LDAF(af[(j + 1) & 1], sbase, j + 1);
                #pragma unroll
                for (int mi = 0; mi < 2; mi++) {
                    mma16(acc[mi][2 * p],     af[j & 1][mi], bf[t % 3][0], bf[t % 3][1]);
                    mma16(acc[mi][2 * p + 1], af[j & 1][mi], bf[t % 3][2], bf[t % 3][3]);
                }
            }
            if (c + 1 < NC) {
                if (c + 2 < NC) { stage(c + 2, (c + 2) % NSTG); CPWAIT1(); }
                else            { CPWAIT0(); }
                __syncthreads();
            }
        }

        // GLU epilogue
        #pragma unroll
        for (int mi = 0; mi < 2; mi++)
            #pragma unroll
            for (int h = 0; h < 2; h++) {
                const int m = m0 + wm * 32 + mi * 16 + g + h * 8;
                if (m < cnt) {
                    __half* gp = g_Gh + (size_t)(pbase + m) * FDIM + nb + wn * 32;
                    #pragma unroll
                    for (int ni = 0; ni < 8; ni++) {
                        const float a  = acc[mi][ni][h * 2];
                        const float gg = acc[mi][ni][h * 2 + 1];
                        gp[ni * 4 + tg] = __float2half(a / (1.f + expf(-a)) * gg);
                    }
                }
            }
        // publish: this (mt, nbi) G slice is ready
        __threadfence();
        __syncthreads();
        if (tid == 0) atomicExch(&g_flag[mt * NY1 + nbi], 1);

    } else {
        // ================= GEMM2: m128 x 128 out cols, K=2816 ================
        const int bx2 = blockIdx.x - G1TILES;
        const int mt  = bx2 % MAXMT;
        const int nbi = bx2 / MAXMT;
        if (mt >= g_tileoff[NEXP]) return;
        int e = 0;
        #pragma unroll
        for (int i = 1; i < NEXP; i++) if (g_tileoff[i] <= mt) e = i;
        const int pbase = g_off[e];
        const int cnt   = g_off[e + 1] - pbase;
        const int m0    = (mt - g_tileoff[e]) * TM;
        const int nb    = nbi * 128;
        const int fbase = mt * NY1;

        const int r = tid >> 1, hh = tid & 1;
        int am = m0 + r; if (am >= cnt) am = cnt - 1;
        const char* asrc = (const char*)(g_Gh + (size_t)(pbase + am) * FDIM) + hh * 64;
        const char* bsrc = (const char*)(g_w2h + ((size_t)e * HDIM + nb + r) * FDIM) + hh * 64;
        uint32_t adst[4];
        #pragma unroll
        for (int i = 0; i < 4; i++)
            adst[i] = sw((uint32_t)(r * 128 + hh * 64 + i * 16));

        auto stage = [&](int c, int s) {
            const uint32_t base = sb + s * STAGE;
            const char* ga = asrc + (size_t)c * 128;
            const char* gb = bsrc + (size_t)c * 128;
            #pragma unroll
            for (int i = 0; i < 4; i++) CP16(base + adst[i], ga + i * 16);
            #pragma unroll
            for (int i = 0; i < 4; i++) CP16(base + adst[i] + 16384, gb + i * 16);
            CPCOMMIT();
        };

        const int NC = FDIM / KB;  // 44 == NY1
        if (tid == 0) { spin_flag(fbase + 0); spin_flag(fbase + 1); }
        __syncthreads();
        stage(0, 0); stage(1, 1);
        CPWAIT1();
        __syncthreads();

        for (int c = 0; c < NC; c++) {
            const uint32_t sbase = sb + (c % NSTG) * STAGE;
            LDAF(af[0], sbase, 0);
            LDBF(bf[0], sbase, 0, 0);
            LDBF(bf[1], sbase, 0, 1);
            #pragma unroll
            for (int t = 0; t < 16; t++) {
                const int j = t >> 2, p = t & 3;
                if (t + 2 < 16) LDBF(bf[(t + 2) % 3], sbase, (t + 2) >> 2, (t + 2) & 3);
                if (p == 1 && j < 3) LDAF(af[(j + 1) & 1], sbase, j + 1);
                #pragma unroll
                for (int mi = 0; mi < 2; mi++) {
                    mma16(acc[mi][2 * p],     af[j & 1][mi], bf[t % 3][0], bf[t % 3][1]);
                    mma16(acc[mi][2 * p + 1], af[j & 1][mi], bf[t % 3][2], bf[t % 3][3]);
                }
            }
            if (c + 1 < NC) {
                if (c + 2 < NC) {
                    if (tid == 0) spin_flag(fbase + c + 2);
                    __syncthreads();                 // all threads see readiness
                    stage(c + 2, (c + 2) % NSTG);
                    CPWAIT1();
                } else CPWAIT0();
                __syncthreads();
            }
        }

        // epilogue: scale by routing score, atomic top-2 combine (deterministic)
        #pragma unroll
        for (int mi = 0; mi < 2; mi++)
            #pragma unroll
            for (int h = 0; h < 2; h++) {
                const int m = m0 + wm * 32 + mi * 16 + g + h * 8;
                if (m < cnt) {
                    const int aid  = g_aid[pbase + m];
                    const float sc = g_scores[aid];
                    float* op = out + (size_t)(aid >> 1) * HDIM + nb + wn * 64;
                    #pragma unroll
                    for (int ni = 0; ni < 8; ni++) {
                        const int c0 = ni * 8 + 2 * tg;
                        atomicAdd(op + c0,     sc * acc[mi][ni][h * 2]);
                        atomicAdd(op + c0 + 1, sc * acc[mi][ni][h * 2 + 1]);
                    }
                }
            }
    }
}

// ---------------- launch ----------------
extern "C" void kernel_launch(void* const* d_in, const int* in_sizes, int n_in,
                              void* d_out, int out_size) {
    const float* x    = (const float*)d_in[0];  // (2,2048,1024)
    const float* wqkv = (const float*)d_in[1];  // (24,1024)
    const float* w1   = (const float*)d_in[2];  // (8,5632,1024)
    const float* w2   = (const float*)d_in[3];  // (8,1024,2816)
    float* out = (float*)d_out;

    cudaFuncSetAttribute(gemm_fused_kernel, cudaFuncAttributeMaxDynamicSharedMemorySize, SMEM_DYN);

    const int conv_units = (NEXP * 2 * FDIM * HDIM + NEXP * HDIM * FDIM) / 8;
    convert_kernel<<<(conv_units + 255) / 256, 256>>>(w1, w2, out);       // 0
    router_kernel<<<N_TOK, 256>>>(x, wqkv);                               // 1
    scatter_kernel<<<(NA + 255) / 256, 256>>>();                          // 2
    gemm_fused_kernel<<<G1TILES + G2TILES, 256, SMEM_DYN>>>(out);         // 3  <- profiled
}

// round 15
// speedup vs baseline: 1.0734x; 1.0544x over previous
#include <cuda_runtime.h>
#include <cuda_fp16.h>
#include <math.h>
#include <stdint.h>

#define N_TOK 4096
#define HDIM  1024
#define FDIM  2816
#define NEXP  8
#define NA    (N_TOK * 2)      // assignments (top-2)
#define TM    128              // m-tile rows
#define KB    64               // k halves per chunk = 128 B per smem row
#define STAGE 32768            // A tile 16KB + B tile 16KB
#define NSTG  3
#define SMEM_DYN (NSTG * STAGE)
#define MAXMT 72               // max total m-tiles: 8192/128 + 7
#define CONV_UNITS ((NEXP * 2 * FDIM * HDIM + NEXP * HDIM * FDIM) / 8)
#define CONV_BLOCKS ((CONV_UNITS + 255) / 256)

// ---------------- scratch (static device allocations only) ----------------
__device__ float g_scores[NA];
__device__ int   g_eids[NA];
__device__ int   g_cnt[NEXP];    // zeroed by gemm1 of the PREVIOUS call (init: .bss zero)
__device__ int   g_fill[NEXP];
__device__ int   g_off[NEXP + 1];
__device__ int   g_tileoff[NEXP + 1];
__device__ int   g_rows[NA];     // sorted pos -> token
__device__ int   g_aid[NA];      // sorted pos -> assignment id
__device__ __align__(16) __half g_xh[(size_t)N_TOK * HDIM];
__device__ __align__(16) __half g_w1h[(size_t)NEXP * 2 * FDIM * HDIM];
__device__ __align__(16) __half g_w2h[(size_t)NEXP * HDIM * FDIM];
__device__ __align__(16) __half g_Gh[(size_t)NA * FDIM];   // GLU output fp16

// ---------------- helpers ----------------
__device__ __forceinline__ uint32_t smem_u32(const void* p) {
    uint32_t a;
    asm("{ .reg .u64 t; cvta.to.shared.u64 t, %1; cvt.u32.u64 %0, t; }" : "=r"(a) : "l"(p));
    return a;
}
__device__ __forceinline__ uint32_t sw(uint32_t off) {   // SW128 swizzle: chunk ^= row&7
    return off ^ ((off >> 3) & 0x70);
}
#define CP16(dst, src) \
    asm volatile("cp.async.cg.shared.global [%0], [%1], 16;" :: "r"(dst), "l"(src))
#define CPCOMMIT() asm volatile("cp.async.commit_group;" ::: "memory")
#define CPWAIT1()  asm volatile("cp.async.wait_group 1;" ::: "memory")
#define CPWAIT0()  asm volatile("cp.async.wait_group 0;" ::: "memory")
#define LDM4(r0, r1, r2, r3, addr) \
    asm volatile("ldmatrix.sync.aligned.m8n8.x4.shared.b16 {%0,%1,%2,%3},[%4];" \
                 : "=r"(r0), "=r"(r1), "=r"(r2), "=r"(r3) : "r"(addr))
__device__ __forceinline__ void mma16(float* d, const uint32_t* a, uint32_t b0, uint32_t b1) {
    asm volatile(
        "mma.sync.aligned.m16n8k16.row.col.f32.f16.f16.f32 "
        "{%0,%1,%2,%3},{%4,%5,%6,%7},{%8,%9},{%0,%1,%2,%3};"
        : "+f"(d[0]), "+f"(d[1]), "+f"(d[2]), "+f"(d[3])
        : "r"(a[0]), "r"(a[1]), "r"(a[2]), "r"(a[3]), "r"(b0), "r"(b1));
}
#define LDAF(dst, sbase, j) do { \
    LDM4((dst)[0][0], (dst)[0][1], (dst)[0][2], (dst)[0][3], (sbase) + sw(aoff[0] + (j) * 32)); \
    LDM4((dst)[1][0], (dst)[1][1], (dst)[1][2], (dst)[1][3], (sbase) + sw(aoff[1] + (j) * 32)); \
} while (0)
#define LDBF(dst, sbase, j, p) \
    LDM4((dst)[0], (dst)[1], (dst)[2], (dst)[3], (sbase) + sw(boff[p] + (j) * 32))

// ---------------- launch 0: FUSED router + weight convert + out zero ----------
// blocks [0, N_TOK): router for token t = blockIdx.x (+ zero out row t, + fp16 x)
// blocks [N_TOK, N_TOK+CONV_BLOCKS): w1/w2 fp32->fp16 convert
__global__ __launch_bounds__(256) void front_kernel(const float* __restrict__ x,
                                                    const float* __restrict__ wqkv,
                                                    const float* __restrict__ w1,
                                                    const float* __restrict__ w2,
                                                    float* __restrict__ out) {
    if (blockIdx.x < N_TOK) {
        // ---------------- router role ----------------
        __shared__ float sx[HDIM];
        __shared__ float sqkv[3 * NEXP];
        const int t = blockIdx.x;
        // zero this token's output row (1024 floats = 256 float4)
        ((float4*)out)[(size_t)t * 256 + threadIdx.x] = make_float4(0.f, 0.f, 0.f, 0.f);
        const float* xr = x + (size_t)t * HDIM;
        for (int i = threadIdx.x; i < HDIM; i += blockDim.x) sx[i] = xr[i];
        __syncthreads();

        for (int i = threadIdx.x; i < HDIM; i += blockDim.x)
            g_xh[(size_t)t * HDIM + i] = __float2half(sx[i]);

        const int w = threadIdx.x >> 5, lane = threadIdx.x & 31;
        #pragma unroll
        for (int r = 0; r < 3; r++) {
            const int j = w + r * NEXP;
            const float* wr = wqkv + (size_t)j * HDIM;
            float s = 0.f;
            for (int i = lane; i < HDIM; i += 32) s += sx[i] * wr[i];
            #pragma unroll
            for (int o = 16; o; o >>= 1) s += __shfl_xor_sync(0xffffffffu, s, o);
            if (lane == 0) sqkv[j] = s;
        }
        __syncthreads();

        if (w == 0) {
            float logit = -1e30f;
            if (lane < NEXP) {
                const float qe = sqkv[lane];
                float a[NEXP], m = -1e30f;
                #pragma unroll
                for (int j = 0; j < NEXP; j++) { a[j] = qe * sqkv[8 + j]; m = fmaxf(m, a[j]); }
                float den = 0.f, num = 0.f;
                #pragma unroll
                for (int j = 0; j < NEXP; j++) {
                    float ee = expf(a[j] - m);
                    den += ee; num += ee * sqkv[16 + j];
                }
                logit = num / den;
            }
            float lg[NEXP];
            #pragma unroll
            for (int e = 0; e < NEXP; e++) lg[e] = __shfl_sync(0xffffffffu, logit, e);
            if (lane == 0) {
                int i0 = 0;
                #pragma unroll
                for (int e = 1; e < NEXP; e++) if (lg[e] > lg[i0]) i0 = e;
                int i1 = (i0 == 0) ? 1 : 0;
                #pragma unroll
                for (int e = 0; e < NEXP; e++) if (e != i1 && e != i0 && lg[e] > lg[i1]) i1 = e;
                const float e1 = expf(lg[i1] - lg[i0]);
                const float inv = 1.f / (1.f + e1);
                g_scores[2 * t]     = inv;
                g_scores[2 * t + 1] = e1 * inv;
                g_eids[2 * t]     = i0;
                g_eids[2 * t + 1] = i1;
                atomicAdd(&g_cnt[i0], 1);
                atomicAdd(&g_cnt[i1], 1);
            }
        }
    } else {
        // ---------------- convert role ----------------
        const size_t U1 = (size_t)NEXP * 2 * FDIM * HDIM / 8;
        const size_t U2 = (size_t)NEXP * HDIM * FDIM / 8;
        const size_t i = (size_t)(blockIdx.x - N_TOK) * 256 + threadIdx.x;
        const float* src;
        __half* dst;
        if (i < U1)           { src = w1 + i * 8;        dst = g_w1h + i * 8; }
        else if (i < U1 + U2) { src = w2 + (i - U1) * 8; dst = g_w2h + (i - U1) * 8; }
        else return;
        const float4 v0 = ((const float4*)src)[0];
        const float4 v1 = ((const float4*)src)[1];
        __half2 h0 = __floats2half2_rn(v0.x, v0.y);
        __half2 h1 = __floats2half2_rn(v0.z, v0.w);
        __half2 h2 = __floats2half2_rn(v1.x, v1.y);
        __half2 h3 = __floats2half2_rn(v1.z, v1.w);
        uint4 o;
        o.x = *(uint32_t*)&h0; o.y = *(uint32_t*)&h1;
        o.z = *(uint32_t*)&h2; o.w = *(uint32_t*)&h3;
        *(uint4*)dst = o;
    }
}

// ---------------- launch 1: scatter (each block re-derives the 8-expert scan) --
__global__ void scatter_kernel() {
    int off[NEXP + 1], tileoff[NEXP + 1];
    int o = 0, tt = 0;
    #pragma unroll
    for (int e = 0; e < NEXP; e++) {
        off[e] = o; tileoff[e] = tt;
        o += g_cnt[e];
        tt += (g_cnt[e] + TM - 1) / TM;
    }
    off[NEXP] = o; tileoff[NEXP] = tt;

    if (blockIdx.x == 0 && threadIdx.x == 0) {
        #pragma unroll
        for (int e = 0; e <= NEXP; e++) { g_off[e] = off[e]; g_tileoff[e] = tileoff[e]; }
    }

    const int a = blockIdx.x * blockDim.x + threadIdx.x;
    if (a < NA) {
        const int e = g_eids[a];
        const int p = off[e] + atomicAdd(&g_fill[e], 1);
        g_aid[p]  = a;
        g_rows[p] = a >> 1;
    }
}

// ---------------- launch 2: grouped GEMM1 (fp16 HMMA) + fused GLU (R10 body) --
__global__ __launch_bounds__(256, 2) void gemm1_kernel() {
    // zero the routing counters for the NEXT call (scatter, their last reader,
    // completed one launch ago; globals are zero-initialized for call #1)
    if (blockIdx.x == 0 && blockIdx.y == 0 && threadIdx.x < NEXP) {
        g_cnt[threadIdx.x] = 0; g_fill[threadIdx.x] = 0;
    }
    const int mt = blockIdx.x;
    if (mt >= g_tileoff[NEXP]) return;
    int e = 0;
    #pragma unroll
    for (int i = 1; i < NEXP; i++) if (g_tileoff[i] <= mt) e = i;
    const int pbase = g_off[e];
    const int cnt   = g_off[e + 1] - pbase;
    const int m0    = (mt - g_tileoff[e]) * TM;
    const int nb    = blockIdx.y * 64;            // GLU col base

    extern __shared__ __align__(1024) char smem[];
    const uint32_t sb = smem_u32(smem);
    const int tid = threadIdx.x, wid = tid >> 5, lane = tid & 31;
    const int wm = wid & 3, wn = wid >> 2;
    const int sel = lane >> 3, li = lane & 7;
    const int g = lane >> 2, tg = lane & 3;

    const int r = tid >> 1, hh = tid & 1;
    int am = m0 + r; if (am >= cnt) am = cnt - 1;
    const char* asrc = (const char*)(g_xh + (size_t)g_rows[pbase + am] * HDIM) + hh * 64;
    const int wrow = e * 2 * FDIM + ((r & 1) ? FDIM : 0) + nb + (r >> 1);  // a/g interleave
    const char* bsrc = (const char*)(g_w1h + (size_t)wrow * HDIM) + hh * 64;
    uint32_t adst[4];
    #pragma unroll
    for (int i = 0; i < 4; i++)
        adst[i] = sw((uint32_t)(r * 128 + hh * 64 + i * 16));

    uint32_t aoff[2], boff[4];
    #pragma unroll
    for (int mi = 0; mi < 2; mi++)
        aoff[mi] = (uint32_t)(wm * 32 + mi * 16 + (sel & 1) * 8 + li) * 128 + (sel >> 1) * 16;
    #pragma unroll
    for (int p = 0; p < 4; p++)
        boff[p] = 16384 + (uint32_t)(wn * 64 + p * 16 + (sel >> 1) * 8 + li) * 128 + (sel & 1) * 16;

    float acc[2][8][4];
    #pragma unroll
    for (int mi = 0; mi < 2; mi++)
        #pragma unroll
        for (int ni = 0; ni < 8; ni++)
            #pragma unroll
            for (int q = 0; q < 4; q++) acc[mi][ni][q] = 0.f;

    auto stage = [&](int c, int s) {
        const uint32_t base = sb + s * STAGE;
        const char* ga = asrc + (size_t)c * 128;
        const char* gb = bsrc + (size_t)c * 128;
        #pragma unroll
        for (int i = 0; i < 4; i++) CP16(base + adst[i], ga + i * 16);
        #pragma unroll
        for (int i = 0; i < 4; i++) CP16(base + adst[i] + 16384, gb + i * 16);
        CPCOMMIT();
    };

    uint32_t af[2][2][4], bf[3][4];
    const int NC = HDIM / KB;  // 16
    stage(0, 0); stage(1, 1);
    CPWAIT1();
    __syncthreads();

    for (int c = 0; c < NC; c++) {
        const uint32_t sbase = sb + (c % NSTG) * STAGE;
        LDAF(af[0], sbase, 0);
        LDBF(bf[0], sbase, 0, 0);
        LDBF(bf[1], sbase, 0, 1);
        #pragma unroll
        for (int t = 0; t < 16; t++) {
            const int j = t >> 2, p = t & 3;
            if (t + 2 < 16) LDBF(bf[(t + 2) % 3], sbase, (t + 2) >> 2, (t + 2) & 3);
            if (p == 1 && j < 3) LDAF(af[(j + 1) & 1], sbase, j + 1);
            #pragma unroll
            for (int mi = 0; mi < 2; mi++) {
                mma16(acc[mi][2 * p],     af[j & 1][mi], bf[t % 3][0], bf[t % 3][1]);
                mma16(acc[mi][2 * p + 1], af[j & 1][mi], bf[t % 3][2], bf[t % 3][3]);
            }
        }
        if (c + 1 < NC) {
            if (c + 2 < NC) { stage(c + 2, (c + 2) % NSTG); CPWAIT1(); }
            else            { CPWAIT0(); }
            __syncthreads();
        }
    }

    // GLU epilogue
    #pragma unroll
    for (int mi = 0; mi < 2; mi++)
        #pragma unroll
        for (int h = 0; h < 2; h++) {
            const int m = m0 + wm * 32 + mi * 16 + g + h * 8;
            if (m < cnt) {
                __half* gp = g_Gh + (size_t)(pbase + m) * FDIM + nb + wn * 32;
                #pragma unroll
                for (int ni = 0; ni < 8; ni++) {
                    const float a  = acc[mi][ni][h * 2];
                    const float gg = acc[mi][ni][h * 2 + 1];
                    gp[ni * 4 + tg] = __float2half(a / (1.f + expf(-a)) * gg);
                }
            }
        }
}

// ---------------- launch 3: grouped GEMM2 (fp16 HMMA, R8 body) + combine ------
__global__ __launch_bounds__(256, 2) void gemm2_kernel(float* __restrict__ out) {
    const int mt = blockIdx.x;
    if (mt >= g_tileoff[NEXP]) return;
    int e = 0;
    #pragma unroll
    for (int i = 1; i < NEXP; i++) if (g_tileoff[i] <= mt) e = i;
    const int pbase = g_off[e];
    const int cnt   = g_off[e + 1] - pbase;
    const int m0    = (mt - g_tileoff[e]) * TM;
    const int nb    = blockIdx.y * 128;           // output col base

    extern __shared__ __align__(1024) char smem[];
    const uint32_t sb = smem_u32(smem);
    const int tid = threadIdx.x, wid = tid >> 5, lane = tid & 31;
    const int wm = wid & 3, wn = wid >> 2;
    const int sel = lane >> 3, li = lane & 7;
    const int g = lane >> 2, tg = lane & 3;

    const int r = tid >> 1, hh = tid & 1;
    int am = m0 + r; if (am >= cnt) am = cnt - 1;
    const char* asrc = (const char*)(g_Gh + (size_t)(pbase + am) * FDIM) + hh * 64;
    const char* bsrc = (const char*)(g_w2h + ((size_t)e * HDIM + nb + r) * FDIM) + hh * 64;
    uint32_t adst[4];
    #pragma unroll
    for (int i = 0; i < 4; i++)
        adst[i] = sw((uint32_t)(r * 128 + hh * 64 + i * 16));

    uint32_t aoff[2], boff[4];
    #pragma unroll
    for (int mi = 0; mi < 2; mi++)
        aoff[mi] = (uint32_t)(wm * 32 + mi * 16 + (sel & 1) * 8 + li) * 128 + (sel >> 1) * 16;
    #pragma unroll
    for (int p = 0; p < 4; p++)
        boff[p] = 16384 + (uint32_t)(wn * 64 + p * 16 + (sel >> 1) * 8 + li) * 128 + (sel & 1) * 16;

    float acc[2][8][4];
    #pragma unroll
    for (int mi = 0; mi < 2; mi++)
        #pragma unroll
        for (int ni = 0; ni < 8; ni++)
            #pragma unroll
            for (int q = 0; q < 4; q++) acc[mi][ni][q] = 0.f;

    auto stage = [&](int c, int s) {
        const uint32_t base = sb + s * STAGE;
        const char* ga = asrc + (size_t)c * 128;
        const char* gb = bsrc + (size_t)c * 128;
        #pragma unroll
        for (int i = 0; i < 4; i++) CP16(base + adst[i], ga + i * 16);
        #pragma unroll
        for (int i = 0; i < 4; i++) CP16(base + adst[i] + 16384, gb + i * 16);
        CPCOMMIT();
    };

    uint32_t af[2][2][4], bf[2][4];
    const int NC = FDIM / KB;  // 44
    stage(0, 0); stage(1, 1);
    CPWAIT1();
    __syncthreads();
    LDAF(af[0], sb, 0);
    LDBF(bf[0], sb, 0, 0);

    for (int c = 0; c < NC; c++) {
        const uint32_t sbase = sb + (c % NSTG) * STAGE;
        #pragma unroll
        for (int j = 0; j < 4; j++) {
            #pragma unroll
            for (int p = 0; p < 4; p++) {
                if (p < 3) {
                    LDBF(bf[(p + 1) & 1], sbase, j, p + 1);
                } else if (j < 3) {
                    LDAF(af[(j + 1) & 1], sbase, j + 1);
                    LDBF(bf[0], sbase, j + 1, 0);
                }
                #pragma unroll
                for (int mi = 0; mi < 2; mi++) {
                    mma16(acc[mi][2 * p],     af[j & 1][mi], bf[p & 1][0], bf[p & 1][1]);
                    mma16(acc[mi][2 * p + 1], af[j & 1][mi], bf[p & 1][2], bf[p & 1][3]);
                }
            }
        }
        if (c + 1 < NC) {
            if (c + 2 < NC) { stage(c + 2, (c + 2) % NSTG); CPWAIT1(); }
            else            { CPWAIT0(); }
            __syncthreads();
            const uint32_t nbase = sb + ((c + 1) % NSTG) * STAGE;
            LDAF(af[0], nbase, 0);
            LDBF(bf[0], nbase, 0, 0);
        }
    }

    // epilogue: scale by routing score, atomic top-2 combine (2 adds/cell -> deterministic)
    #pragma unroll
    for (int mi = 0; mi < 2; mi++)
        #pragma unroll
        for (int h = 0; h < 2; h++) {
            const int m = m0 + wm * 32 + mi * 16 + g + h * 8;
            if (m < cnt) {
                const int aid  = g_aid[pbase + m];
                const float sc = g_scores[aid];
                float* op = out + (size_t)(aid >> 1) * HDIM + nb + wn * 64;
                #pragma unroll
                for (int ni = 0; ni < 8; ni++) {
                    const int c0 = ni * 8 + 2 * tg;
                    atomicAdd(op + c0,     sc * acc[mi][ni][h * 2]);
                    atomicAdd(op + c0 + 1, sc * acc[mi][ni][h * 2 + 1]);
                }
            }
        }
}

// ---------------- launch ----------------
extern "C" void kernel_launch(void* const* d_in, const int* in_sizes, int n_in,
                              void* d_out, int out_size) {
    const float* x    = (const float*)d_in[0];  // (2,2048,1024)
    const float* wqkv = (const float*)d_in[1];  // (24,1024)
    const float* w1   = (const float*)d_in[2];  // (8,5632,1024)
    const float* w2   = (const float*)d_in[3];  // (8,1024,2816)
    float* out = (float*)d_out;

    cudaFuncSetAttribute(gemm1_kernel, cudaFuncAttributeMaxDynamicSharedMemorySize, SMEM_DYN);
    cudaFuncSetAttribute(gemm2_kernel, cudaFuncAttributeMaxDynamicSharedMemorySize, SMEM_DYN);

    front_kernel<<<N_TOK + CONV_BLOCKS, 256>>>(x, wqkv, w1, w2, out);     // 0
    scatter_kernel<<<(NA + 255) / 256, 256>>>();                          // 1
    gemm1_kernel<<<dim3(MAXMT, FDIM / 64), 256, SMEM_DYN>>>();            // 2
    gemm2_kernel<<<dim3(MAXMT, HDIM / 128), 256, SMEM_DYN>>>(out);        // 3  <- profiled
}